// round 14
// baseline (speedup 1.0000x reference)
#include <cuda_runtime.h>
#include <cuda_fp16.h>
#include <cstdint>

// ===========================================================================
// ModulatedConv2d on GB300 — Round 14: R10 + fully hoisted load addressing
//   All cp.async src/dst addresses precomputed before the main loop;
//   per-chunk load code is ~14 cp.async + a few adds (was ~230 instrs with
//   an integer divide). Compute loop identical to R10 (445us best).
// ===========================================================================

#define B_    8
#define CIN   512
#define COUT  512
#define HW    64
#define WDIM  512

// ---- device scratch ----
__device__ float g_s[B_ * CIN];
// W: [b][tap][cout][cin] fp16 (cin contiguous)
__device__ __align__(16) __half g_wh[B_ * 9 * COUT * CIN];
// X: [b][y][x][cin] fp16, each 16-cin group word-permuted [0,4,1,5,2,6,3,7]
__device__ __align__(16) __half g_xh[B_ * HW * HW * CIN];

// ---------------------------------------------------------------------------
__device__ __forceinline__ uint32_t smem_u32(const void* p) {
    uint32_t a;
    asm("{ .reg .u64 t; cvta.to.shared.u64 t, %1; cvt.u32.u64 %0, t; }" : "=r"(a) : "l"(p));
    return a;
}
__device__ __forceinline__ void cp16(uint32_t dst, const void* src, uint32_t n) {
    asm volatile("cp.async.cg.shared.global [%0], [%1], 16, %2;"
                 :: "r"(dst), "l"(src), "r"(n) : "memory");
}
__device__ __forceinline__ void cp_commit() {
    asm volatile("cp.async.commit_group;" ::: "memory");
}
template <int N> __device__ __forceinline__ void cp_wait() {
    asm volatile("cp.async.wait_group %0;" :: "n"(N) : "memory");
}
__device__ __forceinline__ void ldmx4(uint32_t a[4], uint32_t addr) {
    asm volatile("ldmatrix.sync.aligned.m8n8.x4.shared.b16 {%0,%1,%2,%3}, [%4];"
                 : "=r"(a[0]), "=r"(a[1]), "=r"(a[2]), "=r"(a[3]) : "r"(addr));
}
__device__ __forceinline__ void mma16816(float c[4], const uint32_t a[4],
                                         uint32_t b0, uint32_t b1) {
    asm volatile("mma.sync.aligned.m16n8k16.row.col.f32.f16.f16.f32 "
                 "{%0,%1,%2,%3}, {%4,%5,%6,%7}, {%8,%9}, {%0,%1,%2,%3};"
                 : "+f"(c[0]), "+f"(c[1]), "+f"(c[2]), "+f"(c[3])
                 : "r"(a[0]), "r"(a[1]), "r"(a[2]), "r"(a[3]), "r"(b0), "r"(b1));
}

// ---------------------------------------------------------------------------
// Pre-kernels
// ---------------------------------------------------------------------------
__global__ void style_kernel(const float* __restrict__ w,
                             const float* __restrict__ aw,
                             const float* __restrict__ ab) {
    int gwarp = (blockIdx.x * blockDim.x + threadIdx.x) >> 5;
    int lane  = threadIdx.x & 31;
    if (gwarp >= B_ * CIN) return;
    int b = gwarp / CIN, c = gwarp % CIN;
    const float* wr = w + b * WDIM;
    const float* ar = aw + c * WDIM;
    float sum = 0.f;
    #pragma unroll 4
    for (int k = lane; k < WDIM; k += 32) sum += wr[k] * ar[k];
    #pragma unroll
    for (int o = 16; o > 0; o >>= 1) sum += __shfl_xor_sync(0xffffffffu, sum, o);
    if (lane == 0) g_s[gwarp] = sum + ab[c] + 1.0f;
}

// W modulate + demod + quantize, weight read ONCE.
__global__ void wsplit_kernel(const float* __restrict__ weight) {
    __shared__ float red[16];
    __shared__ float dsh;
    const int co = blockIdx.x, ci = threadIdx.x;
    const int lane = ci & 31, wrp = ci >> 5;
    float w9[9];
    #pragma unroll
    for (int t = 0; t < 9; t++) w9[t] = weight[(co * CIN + ci) * 9 + t];
    #pragma unroll 1
    for (int b = 0; b < B_; b++) {
        const float sv = g_s[b * CIN + ci];
        float sum = 0.f;
        #pragma unroll
        for (int t = 0; t < 9; t++) { float v = w9[t] * sv; sum += v * v; }
        #pragma unroll
        for (int o = 16; o > 0; o >>= 1) sum += __shfl_xor_sync(0xffffffffu, sum, o);
        if (lane == 0) red[wrp] = sum;
        __syncthreads();
        if (ci < 16) {
            float v = red[ci];
            #pragma unroll
            for (int o = 8; o > 0; o >>= 1) v += __shfl_xor_sync(0xffffu, v, o, 16);
            if (ci == 0) dsh = rsqrtf(v + 1e-8f);
        }
        __syncthreads();
        const float sd = sv * dsh;
        #pragma unroll
        for (int t = 0; t < 9; t++) {
            int idx = (((b * 9 + t) * COUT) + co) * CIN + ci;
            g_wh[idx] = __float2half_rn(w9[t] * sd);
        }
        __syncthreads();
    }
}

// X quantize + transpose to [b][y][x][cin] fp16, word-permuted per 16-group
__global__ void xsplitT_kernel(const float* __restrict__ x) {
    __shared__ __half shi[64][130];
    int y = blockIdx.x, b = blockIdx.y, tid = threadIdx.x;
    for (int c0 = 0; c0 < CIN; c0 += 128) {
        for (int i = tid; i < 64 * 128; i += 512) {
            int cc = i >> 6, xx = i & 63;
            float v = x[(((size_t)b * CIN + c0 + cc) * HW + y) * HW + xx];
            shi[xx][cc] = __float2half_rn(v);
        }
        __syncthreads();
        for (int i = tid; i < 64 * 64; i += 512) {
            int xx = i >> 6;
            int wi = i & 63;
            int cc = wi << 1;
            int w  = wi & 7;
            int sp = ((w & 3) << 1) | (w >> 2);
            int ccp = (cc & ~15) | (sp << 1);
            size_t o = (((size_t)b * HW + y) * HW + xx) * CIN + c0 + ccp;
            *(uint32_t*)&g_xh[o] = *(const uint32_t*)&shi[xx][cc];
        }
        __syncthreads();
    }
}

// ---------------------------------------------------------------------------
// Main HMMA conv kernel
//   grid = (32 rowpairs, 8 couttiles, 8 b) = 2048 CTAs
//   128 threads (4 warps), warp = 64 cout x 32 px, 4 CTAs/SM
//   K: 32 chunks x 16 cin (9 taps inner). 2-stage cp.async.
//   Load addresses fully precomputed; per-chunk loads = 14 cp.async.
// smem per stage (26880 B):
//   W: [tap9][co64][32B] (ldmatrix-swizzled)  18432 B
//   X: [pos 4x66][32B, word-permuted]          8448 B
// ---------------------------------------------------------------------------
#define ST_BYTES 26880
#define XS_OFF   18432
#define SMEM_TOTAL (2 * ST_BYTES)

__global__ __launch_bounds__(128, 4)
void conv_hmma(const float* __restrict__ noise,
               const float* __restrict__ bias,
               float* __restrict__ out) {
    extern __shared__ __align__(128) char sm[];
    const uint32_t smb = smem_u32(sm);
    const int tid = threadIdx.x, lane = tid & 31, wn = tid >> 5;
    const int y0 = blockIdx.x * 2, cob = blockIdx.y * 64, b = blockIdx.z;
    const int g = lane >> 2, t = lane & 3;

    const int phase = ((blockIdx.x ^ blockIdx.y ^ blockIdx.z) & 3) << 3;

    float acc[4][4][4];
    #pragma unroll
    for (int mf = 0; mf < 4; mf++)
        #pragma unroll
        for (int nf = 0; nf < 4; nf++)
            #pragma unroll
            for (int k = 0; k < 4; k++) acc[mf][nf][k] = 0.f;

    // ldmatrix lane offset; 16B-half h stored at (h ^ ((row>>2)&1))
    const uint32_t lmoff = (uint32_t)((lane & 15) * 32 +
                           ((((lane >> 4) ^ (lane >> 2)) & 1) * 16));

    const __half* xgh = g_xh + (size_t)b * (HW * HW * CIN);

    // ---- precomputed load addressing (invariant up to +cin0 / stage flip) ----
    // W: thread handles (co = tid>>1, h = tid&1) for all 9 taps.
    const int wco = tid >> 1, wh = tid & 1;
    const __half* wsrc0 = g_wh + ((size_t)(b * 9) * COUT + cob + wco) * CIN + wh * 8;
    const uint32_t wdst0 = (uint32_t)(wco * 32 + ((wh ^ ((wco >> 2) & 1)) * 16));
    // X: items i = tid + 128r (r=0..3) and i = tid+512 (tid<16). h2 = tid&1.
    const int h2 = tid & 1;
    int xsrc[5];
    uint32_t xdst[5];
    uint32_t xok[5];
    const int p0 = tid >> 1;
    #pragma unroll
    for (int r = 0; r < 5; r++) {
        const int pos = p0 + 64 * r;          // r=4 only used when tid<16
        const int hy = (pos >= 198) ? 3 : (pos >= 132) ? 2 : (pos >= 66) ? 1 : 0;
        const int hx = pos - 66 * hy;
        const int gy = y0 - 1 + hy;
        const int gx = hx - 1;
        const bool ok = ((unsigned)gy < 64u) && ((unsigned)gx < 64u);
        const int gyc = ok ? gy : 0, gxc = ok ? gx : 0;
        xsrc[r] = (gyc * 64 + gxc) * CIN + h2 * 8;
        xdst[r] = (uint32_t)(pos * 32 + h2 * 16);
        xok[r]  = ok ? 16u : 0u;
    }

    auto load_chunk = [&](int q, int s) {
        const int cin0 = ((q + phase) & 31) << 4;
        const uint32_t wb = smb + s * ST_BYTES;
        const __half* ws = wsrc0 + cin0;
        #pragma unroll
        for (int r = 0; r < 9; r++)
            cp16(wb + r * 2048 + wdst0, ws + (size_t)r * (COUT * CIN), 16);
        const uint32_t xb = wb + XS_OFF;
        const __half* xs = xgh + cin0;
        #pragma unroll
        for (int r = 0; r < 4; r++)
            cp16(xb + xdst[r], xs + xsrc[r], xok[r]);
        if (tid < 16)
            cp16(xb + xdst[4], xs + xsrc[4], xok[4]);
    };

    load_chunk(0, 0);
    cp_commit();

    for (int c = 0; c < 32; c++) {
        const int s = c & 1;
        if (c < 31) { load_chunk(c + 1, s ^ 1); cp_commit(); cp_wait<1>(); }
        else        { cp_wait<0>(); }
        __syncthreads();

        const uint32_t wsm = smb + s * ST_BYTES;
        const char* xhp = sm + s * ST_BYTES + XS_OFF;

        #pragma unroll 3
        for (int tap = 0; tap < 9; tap++) {
            const int dy = tap / 3, dx = tap - dy * 3;
            uint32_t A[4][4];
            #pragma unroll
            for (int mf = 0; mf < 4; mf++)
                ldmx4(A[mf], wsm + tap * 2048 + (uint32_t)((mf * 16) * 32) + lmoff);
            #pragma unroll
            for (int nf = 0; nf < 4; nf++) {
                const int pxb = wn * 32 + nf * 8;
                const int ph = ((pxb >> 6) + dy) * 66 + (pxb & 63) + dx + g;
                const uint2 bb = *(const uint2*)(xhp + ph * 32 + t * 8);
                #pragma unroll
                for (int mf = 0; mf < 4; mf++)
                    mma16816(acc[mf][nf], A[mf], bb.x, bb.y);
            }
        }
        __syncthreads();
    }

    // ---- epilogue: + noise + bias, leaky 0.2 ----
    #pragma unroll
    for (int mf = 0; mf < 4; mf++) {
        const int co = cob + mf * 16 + g;
        const float bi0 = bias[co];
        const float bi8 = bias[co + 8];
        #pragma unroll
        for (int nf = 0; nf < 4; nf++) {
            const int px = wn * 32 + nf * 8 + 2 * t;
            const int y  = y0 + (px >> 6);
            const int xo = px & 63;
            const size_t o0 = (((size_t)(b * COUT + co)) * HW + y) * HW + xo;
            const size_t o1 = o0 + (size_t)8 * HW * HW;
            float2 n0 = *(const float2*)(noise + o0);
            float2 n1 = *(const float2*)(noise + o1);
            float v0 = acc[mf][nf][0] + n0.x + bi0;
            float v1 = acc[mf][nf][1] + n0.y + bi0;
            float v2 = acc[mf][nf][2] + n1.x + bi8;
            float v3 = acc[mf][nf][3] + n1.y + bi8;
            float2 r0, r1;
            r0.x = (v0 >= 0.f) ? v0 : 0.2f * v0;
            r0.y = (v1 >= 0.f) ? v1 : 0.2f * v1;
            r1.x = (v2 >= 0.f) ? v2 : 0.2f * v2;
            r1.y = (v3 >= 0.f) ? v3 : 0.2f * v3;
            *(float2*)(out + o0) = r0;
            *(float2*)(out + o1) = r1;
        }
    }
}

// ---------------------------------------------------------------------------
extern "C" void kernel_launch(void* const* d_in, const int* in_sizes, int n_in,
                              void* d_out, int out_size) {
    const float* x      = (const float*)d_in[0];
    const float* w      = (const float*)d_in[1];
    const float* noise  = (const float*)d_in[2];
    const float* weight = (const float*)d_in[3];
    const float* aw     = (const float*)d_in[4];
    const float* ab     = (const float*)d_in[5];
    const float* bias   = (const float*)d_in[6];
    float* out = (float*)d_out;

    cudaFuncSetAttribute(conv_hmma, cudaFuncAttributeMaxDynamicSharedMemorySize,
                         SMEM_TOTAL);

    style_kernel<<<(B_ * CIN * 32 + 255) / 256, 256>>>(w, aw, ab);
    wsplit_kernel<<<COUT, CIN>>>(weight);
    xsplitT_kernel<<<dim3(HW, B_), 512>>>(x);
    conv_hmma<<<dim3(32, 8, B_), 128, SMEM_TOTAL>>>(noise, bias, out);
}

// round 15
// speedup vs baseline: 1.0395x; 1.0395x over previous
#include <cuda_runtime.h>
#include <cuda_fp16.h>
#include <cstdint>

// ===========================================================================
// ModulatedConv2d on GB300 — Round 15: R10 conv + single-barrier pipeline
//   Loop order wait->sync->issue-next->compute removes the WAR race that
//   forced a second __syncthreads per chunk. wsplit parallelized over b.
// ===========================================================================

#define B_    8
#define CIN   512
#define COUT  512
#define HW    64
#define WDIM  512

// ---- device scratch ----
__device__ float g_s[B_ * CIN];
// W: [b][tap][cout][cin] fp16 (cin contiguous)
__device__ __align__(16) __half g_wh[B_ * 9 * COUT * CIN];
// X: [b][y][x][cin] fp16, each 16-cin group word-permuted [0,4,1,5,2,6,3,7]
__device__ __align__(16) __half g_xh[B_ * HW * HW * CIN];

// ---------------------------------------------------------------------------
__device__ __forceinline__ uint32_t smem_u32(const void* p) {
    uint32_t a;
    asm("{ .reg .u64 t; cvta.to.shared.u64 t, %1; cvt.u32.u64 %0, t; }" : "=r"(a) : "l"(p));
    return a;
}
__device__ __forceinline__ void cp16(uint32_t dst, const void* src, uint32_t n) {
    asm volatile("cp.async.cg.shared.global [%0], [%1], 16, %2;"
                 :: "r"(dst), "l"(src), "r"(n) : "memory");
}
__device__ __forceinline__ void cp_commit() {
    asm volatile("cp.async.commit_group;" ::: "memory");
}
template <int N> __device__ __forceinline__ void cp_wait() {
    asm volatile("cp.async.wait_group %0;" :: "n"(N) : "memory");
}
__device__ __forceinline__ void ldmx4(uint32_t a[4], uint32_t addr) {
    asm volatile("ldmatrix.sync.aligned.m8n8.x4.shared.b16 {%0,%1,%2,%3}, [%4];"
                 : "=r"(a[0]), "=r"(a[1]), "=r"(a[2]), "=r"(a[3]) : "r"(addr));
}
__device__ __forceinline__ void mma16816(float c[4], const uint32_t a[4],
                                         uint32_t b0, uint32_t b1) {
    asm volatile("mma.sync.aligned.m16n8k16.row.col.f32.f16.f16.f32 "
                 "{%0,%1,%2,%3}, {%4,%5,%6,%7}, {%8,%9}, {%0,%1,%2,%3};"
                 : "+f"(c[0]), "+f"(c[1]), "+f"(c[2]), "+f"(c[3])
                 : "r"(a[0]), "r"(a[1]), "r"(a[2]), "r"(a[3]), "r"(b0), "r"(b1));
}

// ---------------------------------------------------------------------------
// Pre-kernels
// ---------------------------------------------------------------------------
__global__ void style_kernel(const float* __restrict__ w,
                             const float* __restrict__ aw,
                             const float* __restrict__ ab) {
    int gwarp = (blockIdx.x * blockDim.x + threadIdx.x) >> 5;
    int lane  = threadIdx.x & 31;
    if (gwarp >= B_ * CIN) return;
    int b = gwarp / CIN, c = gwarp % CIN;
    const float* wr = w + b * WDIM;
    const float* ar = aw + c * WDIM;
    float sum = 0.f;
    #pragma unroll 4
    for (int k = lane; k < WDIM; k += 32) sum += wr[k] * ar[k];
    #pragma unroll
    for (int o = 16; o > 0; o >>= 1) sum += __shfl_xor_sync(0xffffffffu, sum, o);
    if (lane == 0) g_s[gwarp] = sum + ab[c] + 1.0f;
}

// W modulate + demod + quantize; grid (cout, b), 512 threads = cin.
__global__ void wsplit_kernel(const float* __restrict__ weight) {
    __shared__ float red[16];
    __shared__ float dsh;
    const int co = blockIdx.x, b = blockIdx.y, ci = threadIdx.x;
    const int lane = ci & 31, wrp = ci >> 5;
    float w9[9];
    #pragma unroll
    for (int t = 0; t < 9; t++) w9[t] = weight[(co * CIN + ci) * 9 + t];
    const float sv = g_s[b * CIN + ci];
    float sum = 0.f;
    #pragma unroll
    for (int t = 0; t < 9; t++) { float v = w9[t] * sv; sum += v * v; }
    #pragma unroll
    for (int o = 16; o > 0; o >>= 1) sum += __shfl_xor_sync(0xffffffffu, sum, o);
    if (lane == 0) red[wrp] = sum;
    __syncthreads();
    if (ci < 16) {
        float v = red[ci];
        #pragma unroll
        for (int o = 8; o > 0; o >>= 1) v += __shfl_xor_sync(0xffffu, v, o, 16);
        if (ci == 0) dsh = rsqrtf(v + 1e-8f);
    }
    __syncthreads();
    const float sd = sv * dsh;
    #pragma unroll
    for (int t = 0; t < 9; t++) {
        int idx = (((b * 9 + t) * COUT) + co) * CIN + ci;
        g_wh[idx] = __float2half_rn(w9[t] * sd);
    }
}

// X quantize + transpose to [b][y][x][cin] fp16, word-permuted per 16-group
__global__ void xsplitT_kernel(const float* __restrict__ x) {
    __shared__ __half shi[64][130];
    int y = blockIdx.x, b = blockIdx.y, tid = threadIdx.x;
    for (int c0 = 0; c0 < CIN; c0 += 128) {
        for (int i = tid; i < 64 * 128; i += 512) {
            int cc = i >> 6, xx = i & 63;
            float v = x[(((size_t)b * CIN + c0 + cc) * HW + y) * HW + xx];
            shi[xx][cc] = __float2half_rn(v);
        }
        __syncthreads();
        for (int i = tid; i < 64 * 64; i += 512) {
            int xx = i >> 6;
            int wi = i & 63;
            int cc = wi << 1;
            int w  = wi & 7;
            int sp = ((w & 3) << 1) | (w >> 2);
            int ccp = (cc & ~15) | (sp << 1);
            size_t o = (((size_t)b * HW + y) * HW + xx) * CIN + c0 + ccp;
            *(uint32_t*)&g_xh[o] = *(const uint32_t*)&shi[xx][cc];
        }
        __syncthreads();
    }
}

// ---------------------------------------------------------------------------
// Main HMMA conv kernel
//   grid = (32 rowpairs, 8 couttiles, 8 b) = 2048 CTAs
//   128 threads (4 warps), warp = 64 cout x 32 px, 4 CTAs/SM
//   K: 32 chunks x 16 cin (9 taps inner). 2-stage cp.async, ONE sync/chunk.
// smem per stage (26880 B):
//   W: [tap9][co64][32B] (ldmatrix-swizzled)  18432 B
//   X: [pos 4x66][32B, word-permuted]          8448 B
// ---------------------------------------------------------------------------
#define ST_BYTES 26880
#define XS_OFF   18432
#define SMEM_TOTAL (2 * ST_BYTES)

__global__ __launch_bounds__(128, 4)
void conv_hmma(const float* __restrict__ noise,
               const float* __restrict__ bias,
               float* __restrict__ out) {
    extern __shared__ __align__(128) char sm[];
    const uint32_t smb = smem_u32(sm);
    const int tid = threadIdx.x, lane = tid & 31, wn = tid >> 5;
    const int y0 = blockIdx.x * 2, cob = blockIdx.y * 64, b = blockIdx.z;
    const int g = lane >> 2, t = lane & 3;

    const int phase = ((blockIdx.x ^ blockIdx.y ^ blockIdx.z) & 3) << 3;

    float acc[4][4][4];
    #pragma unroll
    for (int mf = 0; mf < 4; mf++)
        #pragma unroll
        for (int nf = 0; nf < 4; nf++)
            #pragma unroll
            for (int k = 0; k < 4; k++) acc[mf][nf][k] = 0.f;

    // ldmatrix lane offset; 16B-half h stored at (h ^ ((row>>2)&1))
    const uint32_t lmoff = (uint32_t)((lane & 15) * 32 +
                           ((((lane >> 4) ^ (lane >> 2)) & 1) * 16));

    const __half* wgbase = g_wh + ((size_t)(b * 9) * COUT + cob) * CIN;
    const __half* xgh = g_xh + (size_t)b * (HW * HW * CIN);

    auto load_chunk = [&](int q, int s) {
        const int cin0 = ((q + phase) & 31) << 4;
        const uint32_t wb = smb + s * ST_BYTES;
        for (int i = tid; i < 1152; i += 128) {
            int tap = i >> 7;
            int j   = i & 127;
            int co  = j >> 1;
            int h   = j & 1;
            const __half* src = wgbase + (size_t)tap * (COUT * CIN) + co * CIN + cin0 + h * 8;
            cp16(wb + tap * 2048 + co * 32 + ((h ^ ((co >> 2) & 1)) * 16), src, 16);
        }
        const uint32_t xb = wb + XS_OFF;
        for (int i = tid; i < 528; i += 128) {
            int pos = i >> 1;
            int h2  = i & 1;
            int hy  = pos / 66;
            int hx  = pos - hy * 66;
            int gy = y0 - 1 + hy;
            int gx = hx - 1;
            bool ok = ((unsigned)gy < 64u) && ((unsigned)gx < 64u);
            int gyc = ok ? gy : 0, gxc = ok ? gx : 0;
            const __half* src = xgh + ((size_t)(gyc * 64 + gxc)) * CIN + cin0 + h2 * 8;
            cp16(xb + pos * 32 + h2 * 16, src, ok ? 16u : 0u);
        }
    };

    // prologue: stage 0 in flight
    load_chunk(0, 0);
    cp_commit();

    for (int c = 0; c < 32; c++) {
        const int s = c & 1;
        // wait for chunk c's data (issued last iteration; latency covered)
        cp_wait<0>();
        __syncthreads();
        // stage s^1 fully consumed by all warps (chunk c-1) -> safe to refill
        if (c < 31) load_chunk(c + 1, s ^ 1);
        cp_commit();

        const uint32_t wsm = smb + s * ST_BYTES;
        const char* xhp = sm + s * ST_BYTES + XS_OFF;

        #pragma unroll 3
        for (int tap = 0; tap < 9; tap++) {
            const int dy = tap / 3, dx = tap - dy * 3;
            uint32_t A[4][4];
            #pragma unroll
            for (int mf = 0; mf < 4; mf++)
                ldmx4(A[mf], wsm + tap * 2048 + (uint32_t)((mf * 16) * 32) + lmoff);
            #pragma unroll
            for (int nf = 0; nf < 4; nf++) {
                const int pxb = wn * 32 + nf * 8;
                const int ph = ((pxb >> 6) + dy) * 66 + (pxb & 63) + dx + g;
                const uint2 bb = *(const uint2*)(xhp + ph * 32 + t * 8);
                #pragma unroll
                for (int mf = 0; mf < 4; mf++)
                    mma16816(acc[mf][nf], A[mf], bb.x, bb.y);
            }
        }
    }

    // ---- epilogue: + noise + bias, leaky 0.2 ----
    #pragma unroll
    for (int mf = 0; mf < 4; mf++) {
        const int co = cob + mf * 16 + g;
        const float bi0 = bias[co];
        const float bi8 = bias[co + 8];
        #pragma unroll
        for (int nf = 0; nf < 4; nf++) {
            const int px = wn * 32 + nf * 8 + 2 * t;
            const int y  = y0 + (px >> 6);
            const int xo = px & 63;
            const size_t o0 = (((size_t)(b * COUT + co)) * HW + y) * HW + xo;
            const size_t o1 = o0 + (size_t)8 * HW * HW;
            float2 n0 = *(const float2*)(noise + o0);
            float2 n1 = *(const float2*)(noise + o1);
            float v0 = acc[mf][nf][0] + n0.x + bi0;
            float v1 = acc[mf][nf][1] + n0.y + bi0;
            float v2 = acc[mf][nf][2] + n1.x + bi8;
            float v3 = acc[mf][nf][3] + n1.y + bi8;
            float2 r0, r1;
            r0.x = (v0 >= 0.f) ? v0 : 0.2f * v0;
            r0.y = (v1 >= 0.f) ? v1 : 0.2f * v1;
            r1.x = (v2 >= 0.f) ? v2 : 0.2f * v2;
            r1.y = (v3 >= 0.f) ? v3 : 0.2f * v3;
            *(float2*)(out + o0) = r0;
            *(float2*)(out + o1) = r1;
        }
    }
}

// ---------------------------------------------------------------------------
extern "C" void kernel_launch(void* const* d_in, const int* in_sizes, int n_in,
                              void* d_out, int out_size) {
    const float* x      = (const float*)d_in[0];
    const float* w      = (const float*)d_in[1];
    const float* noise  = (const float*)d_in[2];
    const float* weight = (const float*)d_in[3];
    const float* aw     = (const float*)d_in[4];
    const float* ab     = (const float*)d_in[5];
    const float* bias   = (const float*)d_in[6];
    float* out = (float*)d_out;

    cudaFuncSetAttribute(conv_hmma, cudaFuncAttributeMaxDynamicSharedMemorySize,
                         SMEM_TOTAL);

    style_kernel<<<(B_ * CIN * 32 + 255) / 256, 256>>>(w, aw, ab);
    wsplit_kernel<<<dim3(COUT, B_), CIN>>>(weight);
    xsplitT_kernel<<<dim3(HW, B_), 512>>>(x);
    conv_hmma<<<dim3(32, 8, B_), 128, SMEM_TOTAL>>>(noise, bias, out);
}

// round 16
// speedup vs baseline: 1.0458x; 1.0061x over previous
#include <cuda_runtime.h>
#include <cuda_fp16.h>
#include <cstdint>

// ===========================================================================
// ModulatedConv2d on GB300 — Round 16: R15 + per-warp tap rotation
//   Each warp traverses the 9 taps starting at (2*wn)%9 so co-resident
//   warps' LDSM/LDS bursts desynchronize on the shared smem crossbar
//   instead of colliding at every tap boundary.
// ===========================================================================

#define B_    8
#define CIN   512
#define COUT  512
#define HW    64
#define WDIM  512

// ---- device scratch ----
__device__ float g_s[B_ * CIN];
// W: [b][tap][cout][cin] fp16 (cin contiguous)
__device__ __align__(16) __half g_wh[B_ * 9 * COUT * CIN];
// X: [b][y][x][cin] fp16, each 16-cin group word-permuted [0,4,1,5,2,6,3,7]
__device__ __align__(16) __half g_xh[B_ * HW * HW * CIN];

// ---------------------------------------------------------------------------
__device__ __forceinline__ uint32_t smem_u32(const void* p) {
    uint32_t a;
    asm("{ .reg .u64 t; cvta.to.shared.u64 t, %1; cvt.u32.u64 %0, t; }" : "=r"(a) : "l"(p));
    return a;
}
__device__ __forceinline__ void cp16(uint32_t dst, const void* src, uint32_t n) {
    asm volatile("cp.async.cg.shared.global [%0], [%1], 16, %2;"
                 :: "r"(dst), "l"(src), "r"(n) : "memory");
}
__device__ __forceinline__ void cp_commit() {
    asm volatile("cp.async.commit_group;" ::: "memory");
}
template <int N> __device__ __forceinline__ void cp_wait() {
    asm volatile("cp.async.wait_group %0;" :: "n"(N) : "memory");
}
__device__ __forceinline__ void ldmx4(uint32_t a[4], uint32_t addr) {
    asm volatile("ldmatrix.sync.aligned.m8n8.x4.shared.b16 {%0,%1,%2,%3}, [%4];"
                 : "=r"(a[0]), "=r"(a[1]), "=r"(a[2]), "=r"(a[3]) : "r"(addr));
}
__device__ __forceinline__ void mma16816(float c[4], const uint32_t a[4],
                                         uint32_t b0, uint32_t b1) {
    asm volatile("mma.sync.aligned.m16n8k16.row.col.f32.f16.f16.f32 "
                 "{%0,%1,%2,%3}, {%4,%5,%6,%7}, {%8,%9}, {%0,%1,%2,%3};"
                 : "+f"(c[0]), "+f"(c[1]), "+f"(c[2]), "+f"(c[3])
                 : "r"(a[0]), "r"(a[1]), "r"(a[2]), "r"(a[3]), "r"(b0), "r"(b1));
}

// ---------------------------------------------------------------------------
// Pre-kernels
// ---------------------------------------------------------------------------
__global__ void style_kernel(const float* __restrict__ w,
                             const float* __restrict__ aw,
                             const float* __restrict__ ab) {
    int gwarp = (blockIdx.x * blockDim.x + threadIdx.x) >> 5;
    int lane  = threadIdx.x & 31;
    if (gwarp >= B_ * CIN) return;
    int b = gwarp / CIN, c = gwarp % CIN;
    const float* wr = w + b * WDIM;
    const float* ar = aw + c * WDIM;
    float sum = 0.f;
    #pragma unroll 4
    for (int k = lane; k < WDIM; k += 32) sum += wr[k] * ar[k];
    #pragma unroll
    for (int o = 16; o > 0; o >>= 1) sum += __shfl_xor_sync(0xffffffffu, sum, o);
    if (lane == 0) g_s[gwarp] = sum + ab[c] + 1.0f;
}

// W modulate + demod + quantize; grid (cout, b), 512 threads = cin.
__global__ void wsplit_kernel(const float* __restrict__ weight) {
    __shared__ float red[16];
    __shared__ float dsh;
    const int co = blockIdx.x, b = blockIdx.y, ci = threadIdx.x;
    const int lane = ci & 31, wrp = ci >> 5;
    float w9[9];
    #pragma unroll
    for (int t = 0; t < 9; t++) w9[t] = weight[(co * CIN + ci) * 9 + t];
    const float sv = g_s[b * CIN + ci];
    float sum = 0.f;
    #pragma unroll
    for (int t = 0; t < 9; t++) { float v = w9[t] * sv; sum += v * v; }
    #pragma unroll
    for (int o = 16; o > 0; o >>= 1) sum += __shfl_xor_sync(0xffffffffu, sum, o);
    if (lane == 0) red[wrp] = sum;
    __syncthreads();
    if (ci < 16) {
        float v = red[ci];
        #pragma unroll
        for (int o = 8; o > 0; o >>= 1) v += __shfl_xor_sync(0xffffu, v, o, 16);
        if (ci == 0) dsh = rsqrtf(v + 1e-8f);
    }
    __syncthreads();
    const float sd = sv * dsh;
    #pragma unroll
    for (int t = 0; t < 9; t++) {
        int idx = (((b * 9 + t) * COUT) + co) * CIN + ci;
        g_wh[idx] = __float2half_rn(w9[t] * sd);
    }
}

// X quantize + transpose to [b][y][x][cin] fp16, word-permuted per 16-group
__global__ void xsplitT_kernel(const float* __restrict__ x) {
    __shared__ __half shi[64][130];
    int y = blockIdx.x, b = blockIdx.y, tid = threadIdx.x;
    for (int c0 = 0; c0 < CIN; c0 += 128) {
        for (int i = tid; i < 64 * 128; i += 512) {
            int cc = i >> 6, xx = i & 63;
            float v = x[(((size_t)b * CIN + c0 + cc) * HW + y) * HW + xx];
            shi[xx][cc] = __float2half_rn(v);
        }
        __syncthreads();
        for (int i = tid; i < 64 * 64; i += 512) {
            int xx = i >> 6;
            int wi = i & 63;
            int cc = wi << 1;
            int w  = wi & 7;
            int sp = ((w & 3) << 1) | (w >> 2);
            int ccp = (cc & ~15) | (sp << 1);
            size_t o = (((size_t)b * HW + y) * HW + xx) * CIN + c0 + ccp;
            *(uint32_t*)&g_xh[o] = *(const uint32_t*)&shi[xx][cc];
        }
        __syncthreads();
    }
}

// ---------------------------------------------------------------------------
// Main HMMA conv kernel
//   grid = (32 rowpairs, 8 couttiles, 8 b) = 2048 CTAs
//   128 threads (4 warps), warp = 64 cout x 32 px, 4 CTAs/SM
//   K: 32 chunks x 16 cin (9 taps inner, per-warp rotated). 2-stage, 1 sync.
// smem per stage (26880 B):
//   W: [tap9][co64][32B] (ldmatrix-swizzled)  18432 B
//   X: [pos 4x66][32B, word-permuted]          8448 B
// ---------------------------------------------------------------------------
#define ST_BYTES 26880
#define XS_OFF   18432
#define SMEM_TOTAL (2 * ST_BYTES)

__global__ __launch_bounds__(128, 4)
void conv_hmma(const float* __restrict__ noise,
               const float* __restrict__ bias,
               float* __restrict__ out) {
    extern __shared__ __align__(128) char sm[];
    const uint32_t smb = smem_u32(sm);
    const int tid = threadIdx.x, lane = tid & 31, wn = tid >> 5;
    const int y0 = blockIdx.x * 2, cob = blockIdx.y * 64, b = blockIdx.z;
    const int g = lane >> 2, t = lane & 3;

    const int phase = ((blockIdx.x ^ blockIdx.y ^ blockIdx.z) & 3) << 3;
    const int tbase = (wn * 2) % 9;       // per-warp tap rotation: 0,2,4,6

    float acc[4][4][4];
    #pragma unroll
    for (int mf = 0; mf < 4; mf++)
        #pragma unroll
        for (int nf = 0; nf < 4; nf++)
            #pragma unroll
            for (int k = 0; k < 4; k++) acc[mf][nf][k] = 0.f;

    // ldmatrix lane offset; 16B-half h stored at (h ^ ((row>>2)&1))
    const uint32_t lmoff = (uint32_t)((lane & 15) * 32 +
                           ((((lane >> 4) ^ (lane >> 2)) & 1) * 16));

    const __half* wgbase = g_wh + ((size_t)(b * 9) * COUT + cob) * CIN;
    const __half* xgh = g_xh + (size_t)b * (HW * HW * CIN);

    auto load_chunk = [&](int q, int s) {
        const int cin0 = ((q + phase) & 31) << 4;
        const uint32_t wb = smb + s * ST_BYTES;
        for (int i = tid; i < 1152; i += 128) {
            int tap = i >> 7;
            int j   = i & 127;
            int co  = j >> 1;
            int h   = j & 1;
            const __half* src = wgbase + (size_t)tap * (COUT * CIN) + co * CIN + cin0 + h * 8;
            cp16(wb + tap * 2048 + co * 32 + ((h ^ ((co >> 2) & 1)) * 16), src, 16);
        }
        const uint32_t xb = wb + XS_OFF;
        for (int i = tid; i < 528; i += 128) {
            int pos = i >> 1;
            int h2  = i & 1;
            int hy  = pos / 66;
            int hx  = pos - hy * 66;
            int gy = y0 - 1 + hy;
            int gx = hx - 1;
            bool ok = ((unsigned)gy < 64u) && ((unsigned)gx < 64u);
            int gyc = ok ? gy : 0, gxc = ok ? gx : 0;
            const __half* src = xgh + ((size_t)(gyc * 64 + gxc)) * CIN + cin0 + h2 * 8;
            cp16(xb + pos * 32 + h2 * 16, src, ok ? 16u : 0u);
        }
    };

    // prologue: stage 0 in flight
    load_chunk(0, 0);
    cp_commit();

    const int pxb_row = (wn * 32) >> 6;
    const int pxb_col = (wn * 32) & 63;

    for (int c = 0; c < 32; c++) {
        const int s = c & 1;
        cp_wait<0>();
        __syncthreads();
        if (c < 31) load_chunk(c + 1, s ^ 1);
        cp_commit();

        const uint32_t wsm = smb + s * ST_BYTES;
        const char* xhp = sm + s * ST_BYTES + XS_OFF;

        #pragma unroll
        for (int tt = 0; tt < 9; tt++) {
            int tap = tbase + tt;
            if (tap >= 9) tap -= 9;               // rotated, runtime tap
            const int dy = tap / 3;               // mul-high div by 3
            const int dx = tap - dy * 3;
            uint32_t A[4][4];
            const uint32_t wtap = wsm + (uint32_t)tap * 2048;
            #pragma unroll
            for (int mf = 0; mf < 4; mf++)
                ldmx4(A[mf], wtap + (uint32_t)((mf * 16) * 32) + lmoff);
            const int phb = (pxb_row + dy) * 66 + pxb_col + dx + g;
            #pragma unroll
            for (int nf = 0; nf < 4; nf++) {
                const uint2 bb = *(const uint2*)(xhp + (phb + nf * 8) * 32 + t * 8);
                #pragma unroll
                for (int mf = 0; mf < 4; mf++)
                    mma16816(acc[mf][nf], A[mf], bb.x, bb.y);
            }
        }
    }

    // ---- epilogue: + noise + bias, leaky 0.2 ----
    #pragma unroll
    for (int mf = 0; mf < 4; mf++) {
        const int co = cob + mf * 16 + g;
        const float bi0 = bias[co];
        const float bi8 = bias[co + 8];
        #pragma unroll
        for (int nf = 0; nf < 4; nf++) {
            const int px = wn * 32 + nf * 8 + 2 * t;
            const int y  = y0 + (px >> 6);
            const int xo = px & 63;
            const size_t o0 = (((size_t)(b * COUT + co)) * HW + y) * HW + xo;
            const size_t o1 = o0 + (size_t)8 * HW * HW;
            float2 n0 = *(const float2*)(noise + o0);
            float2 n1 = *(const float2*)(noise + o1);
            float v0 = acc[mf][nf][0] + n0.x + bi0;
            float v1 = acc[mf][nf][1] + n0.y + bi0;
            float v2 = acc[mf][nf][2] + n1.x + bi8;
            float v3 = acc[mf][nf][3] + n1.y + bi8;
            float2 r0, r1;
            r0.x = (v0 >= 0.f) ? v0 : 0.2f * v0;
            r0.y = (v1 >= 0.f) ? v1 : 0.2f * v1;
            r1.x = (v2 >= 0.f) ? v2 : 0.2f * v2;
            r1.y = (v3 >= 0.f) ? v3 : 0.2f * v3;
            *(float2*)(out + o0) = r0;
            *(float2*)(out + o1) = r1;
        }
    }
}

// ---------------------------------------------------------------------------
extern "C" void kernel_launch(void* const* d_in, const int* in_sizes, int n_in,
                              void* d_out, int out_size) {
    const float* x      = (const float*)d_in[0];
    const float* w      = (const float*)d_in[1];
    const float* noise  = (const float*)d_in[2];
    const float* weight = (const float*)d_in[3];
    const float* aw     = (const float*)d_in[4];
    const float* ab     = (const float*)d_in[5];
    const float* bias   = (const float*)d_in[6];
    float* out = (float*)d_out;

    cudaFuncSetAttribute(conv_hmma, cudaFuncAttributeMaxDynamicSharedMemorySize,
                         SMEM_TOTAL);

    style_kernel<<<(B_ * CIN * 32 + 255) / 256, 256>>>(w, aw, ab);
    wsplit_kernel<<<dim3(COUT, B_), CIN>>>(weight);
    xsplitT_kernel<<<dim3(HW, B_), 512>>>(x);
    conv_hmma<<<dim3(32, 8, B_), 128, SMEM_TOTAL>>>(noise, bias, out);
}

// round 17
// speedup vs baseline: 1.1066x; 1.0581x over previous
#include <cuda_runtime.h>
#include <cuda_fp16.h>
#include <cstdint>

// ===========================================================================
// ModulatedConv2d on GB300 — Round 17: square warp tiles (64co x 64px)
//   CTA = 64co x 256px (4 rows), 4 warps = 1 row each, 3 CTAs/SM.
//   A-frag smem traffic per MMA halves (192B -> 128B per MMA): the crossbar
//   phase now fits in the tensor shadow instead of co-binding with it.
// ===========================================================================

#define B_    8
#define CIN   512
#define COUT  512
#define HW    64
#define WDIM  512

// ---- device scratch ----
__device__ float g_s[B_ * CIN];
// W: [b][tap][cout][cin] fp16 (cin contiguous)
__device__ __align__(16) __half g_wh[B_ * 9 * COUT * CIN];
// X: [b][y][x][cin] fp16, each 16-cin group word-permuted [0,4,1,5,2,6,3,7]
__device__ __align__(16) __half g_xh[B_ * HW * HW * CIN];

// ---------------------------------------------------------------------------
__device__ __forceinline__ uint32_t smem_u32(const void* p) {
    uint32_t a;
    asm("{ .reg .u64 t; cvta.to.shared.u64 t, %1; cvt.u32.u64 %0, t; }" : "=r"(a) : "l"(p));
    return a;
}
__device__ __forceinline__ void cp16(uint32_t dst, const void* src, uint32_t n) {
    asm volatile("cp.async.cg.shared.global [%0], [%1], 16, %2;"
                 :: "r"(dst), "l"(src), "r"(n) : "memory");
}
__device__ __forceinline__ void cp_commit() {
    asm volatile("cp.async.commit_group;" ::: "memory");
}
template <int N> __device__ __forceinline__ void cp_wait() {
    asm volatile("cp.async.wait_group %0;" :: "n"(N) : "memory");
}
__device__ __forceinline__ void ldmx4(uint32_t a[4], uint32_t addr) {
    asm volatile("ldmatrix.sync.aligned.m8n8.x4.shared.b16 {%0,%1,%2,%3}, [%4];"
                 : "=r"(a[0]), "=r"(a[1]), "=r"(a[2]), "=r"(a[3]) : "r"(addr));
}
__device__ __forceinline__ void mma16816(float c[4], const uint32_t a[4],
                                         uint32_t b0, uint32_t b1) {
    asm volatile("mma.sync.aligned.m16n8k16.row.col.f32.f16.f16.f32 "
                 "{%0,%1,%2,%3}, {%4,%5,%6,%7}, {%8,%9}, {%0,%1,%2,%3};"
                 : "+f"(c[0]), "+f"(c[1]), "+f"(c[2]), "+f"(c[3])
                 : "r"(a[0]), "r"(a[1]), "r"(a[2]), "r"(a[3]), "r"(b0), "r"(b1));
}

// ---------------------------------------------------------------------------
// Pre-kernels
// ---------------------------------------------------------------------------
__global__ void style_kernel(const float* __restrict__ w,
                             const float* __restrict__ aw,
                             const float* __restrict__ ab) {
    int gwarp = (blockIdx.x * blockDim.x + threadIdx.x) >> 5;
    int lane  = threadIdx.x & 31;
    if (gwarp >= B_ * CIN) return;
    int b = gwarp / CIN, c = gwarp % CIN;
    const float* wr = w + b * WDIM;
    const float* ar = aw + c * WDIM;
    float sum = 0.f;
    #pragma unroll 4
    for (int k = lane; k < WDIM; k += 32) sum += wr[k] * ar[k];
    #pragma unroll
    for (int o = 16; o > 0; o >>= 1) sum += __shfl_xor_sync(0xffffffffu, sum, o);
    if (lane == 0) g_s[gwarp] = sum + ab[c] + 1.0f;
}

// W modulate + demod + quantize; grid (cout, b), 512 threads = cin.
__global__ void wsplit_kernel(const float* __restrict__ weight) {
    __shared__ float red[16];
    __shared__ float dsh;
    const int co = blockIdx.x, b = blockIdx.y, ci = threadIdx.x;
    const int lane = ci & 31, wrp = ci >> 5;
    float w9[9];
    #pragma unroll
    for (int t = 0; t < 9; t++) w9[t] = weight[(co * CIN + ci) * 9 + t];
    const float sv = g_s[b * CIN + ci];
    float sum = 0.f;
    #pragma unroll
    for (int t = 0; t < 9; t++) { float v = w9[t] * sv; sum += v * v; }
    #pragma unroll
    for (int o = 16; o > 0; o >>= 1) sum += __shfl_xor_sync(0xffffffffu, sum, o);
    if (lane == 0) red[wrp] = sum;
    __syncthreads();
    if (ci < 16) {
        float v = red[ci];
        #pragma unroll
        for (int o = 8; o > 0; o >>= 1) v += __shfl_xor_sync(0xffffu, v, o, 16);
        if (ci == 0) dsh = rsqrtf(v + 1e-8f);
    }
    __syncthreads();
    const float sd = sv * dsh;
    #pragma unroll
    for (int t = 0; t < 9; t++) {
        int idx = (((b * 9 + t) * COUT) + co) * CIN + ci;
        g_wh[idx] = __float2half_rn(w9[t] * sd);
    }
}

// X quantize + transpose to [b][y][x][cin] fp16, word-permuted per 16-group
__global__ void xsplitT_kernel(const float* __restrict__ x) {
    __shared__ __half shi[64][130];
    int y = blockIdx.x, b = blockIdx.y, tid = threadIdx.x;
    for (int c0 = 0; c0 < CIN; c0 += 128) {
        for (int i = tid; i < 64 * 128; i += 512) {
            int cc = i >> 6, xx = i & 63;
            float v = x[(((size_t)b * CIN + c0 + cc) * HW + y) * HW + xx];
            shi[xx][cc] = __float2half_rn(v);
        }
        __syncthreads();
        for (int i = tid; i < 64 * 64; i += 512) {
            int xx = i >> 6;
            int wi = i & 63;
            int cc = wi << 1;
            int w  = wi & 7;
            int sp = ((w & 3) << 1) | (w >> 2);
            int ccp = (cc & ~15) | (sp << 1);
            size_t o = (((size_t)b * HW + y) * HW + xx) * CIN + c0 + ccp;
            *(uint32_t*)&g_xh[o] = *(const uint32_t*)&shi[xx][cc];
        }
        __syncthreads();
    }
}

// ---------------------------------------------------------------------------
// Main HMMA conv kernel
//   grid = (16 rowquads, 8 couttiles, 8 b) = 1024 CTAs
//   128 threads (4 warps), warp = 64 cout x 64 px (1 image row), 3 CTAs/SM
//   K: 32 chunks x 16 cin (9 taps inner, per-warp rotated). 2-stage, 1 sync.
// smem per stage (31104 B):
//   W: [tap9][co64][32B] (ldmatrix-swizzled)  18432 B
//   X: [pos 6x66][32B, word-permuted]         12672 B
// ---------------------------------------------------------------------------
#define ST_BYTES 31104
#define XS_OFF   18432
#define SMEM_TOTAL (2 * ST_BYTES)

__global__ __launch_bounds__(128, 3)
void conv_hmma(const float* __restrict__ noise,
               const float* __restrict__ bias,
               float* __restrict__ out) {
    extern __shared__ __align__(128) char sm[];
    const uint32_t smb = smem_u32(sm);
    const int tid = threadIdx.x, lane = tid & 31, wn = tid >> 5;
    const int y0 = blockIdx.x * 4, cob = blockIdx.y * 64, b = blockIdx.z;
    const int g = lane >> 2, t = lane & 3;

    const int phase = ((blockIdx.x ^ blockIdx.y ^ blockIdx.z) & 3) << 3;
    const int tbase = (wn * 2) % 9;       // per-warp tap rotation

    float acc[4][8][4];                   // mf x nf x frag = 128 floats
    #pragma unroll
    for (int mf = 0; mf < 4; mf++)
        #pragma unroll
        for (int nf = 0; nf < 8; nf++)
            #pragma unroll
            for (int k = 0; k < 4; k++) acc[mf][nf][k] = 0.f;

    // ldmatrix lane offset; 16B-half h stored at (h ^ ((row>>2)&1))
    const uint32_t lmoff = (uint32_t)((lane & 15) * 32 +
                           ((((lane >> 4) ^ (lane >> 2)) & 1) * 16));

    const __half* wgbase = g_wh + ((size_t)(b * 9) * COUT + cob) * CIN;
    const __half* xgh = g_xh + (size_t)b * (HW * HW * CIN);

    auto load_chunk = [&](int q, int s) {
        const int cin0 = ((q + phase) & 31) << 4;
        const uint32_t wb = smb + s * ST_BYTES;
        // W: 9 taps x 64 co x 2 halves = 1152 x 16B
        for (int i = tid; i < 1152; i += 128) {
            int tap = i >> 7;
            int j   = i & 127;
            int co  = j >> 1;
            int h   = j & 1;
            const __half* src = wgbase + (size_t)tap * (COUT * CIN) + co * CIN + cin0 + h * 8;
            cp16(wb + tap * 2048 + co * 32 + ((h ^ ((co >> 2) & 1)) * 16), src, 16);
        }
        // X: 6 halo rows x 66 pos x 2 halves = 792 x 16B, zero-fill OOB
        const uint32_t xb = wb + XS_OFF;
        for (int i = tid; i < 792; i += 128) {
            int pos = i >> 1;
            int h2  = i & 1;
            int hy  = pos / 66;
            int hx  = pos - hy * 66;
            int gy = y0 - 1 + hy;
            int gx = hx - 1;
            bool ok = ((unsigned)gy < 64u) && ((unsigned)gx < 64u);
            int gyc = ok ? gy : 0, gxc = ok ? gx : 0;
            const __half* src = xgh + ((size_t)(gyc * 64 + gxc)) * CIN + cin0 + h2 * 8;
            cp16(xb + pos * 32 + h2 * 16, src, ok ? 16u : 0u);
        }
    };

    load_chunk(0, 0);
    cp_commit();

    for (int c = 0; c < 32; c++) {
        const int s = c & 1;
        cp_wait<0>();
        __syncthreads();
        if (c < 31) load_chunk(c + 1, s ^ 1);
        cp_commit();

        const uint32_t wsm = smb + s * ST_BYTES;
        const char* xhp = sm + s * ST_BYTES + XS_OFF;

        #pragma unroll
        for (int tt = 0; tt < 9; tt++) {
            int tap = tbase + tt;
            if (tap >= 9) tap -= 9;
            const int dy = tap / 3;
            const int dx = tap - dy * 3;
            uint32_t A[4][4];
            const uint32_t wtap = wsm + (uint32_t)tap * 2048;
            #pragma unroll
            for (int mf = 0; mf < 4; mf++)
                ldmx4(A[mf], wtap + (uint32_t)((mf * 16) * 32) + lmoff);
            // warp handles image row (y0 + wn); B pos row = wn + dy
            const int phb = (wn + dy) * 66 + dx + g;
            #pragma unroll
            for (int nf = 0; nf < 8; nf++) {
                const uint2 bb = *(const uint2*)(xhp + (phb + nf * 8) * 32 + t * 8);
                #pragma unroll
                for (int mf = 0; mf < 4; mf++)
                    mma16816(acc[mf][nf], A[mf], bb.x, bb.y);
            }
        }
    }

    // ---- epilogue: + noise + bias, leaky 0.2 ----
    const int y = y0 + wn;
    #pragma unroll
    for (int mf = 0; mf < 4; mf++) {
        const int co = cob + mf * 16 + g;
        const float bi0 = bias[co];
        const float bi8 = bias[co + 8];
        #pragma unroll
        for (int nf = 0; nf < 8; nf++) {
            const int xo = nf * 8 + 2 * t;
            const size_t o0 = (((size_t)(b * COUT + co)) * HW + y) * HW + xo;
            const size_t o1 = o0 + (size_t)8 * HW * HW;
            float2 n0 = *(const float2*)(noise + o0);
            float2 n1 = *(const float2*)(noise + o1);
            float v0 = acc[mf][nf][0] + n0.x + bi0;
            float v1 = acc[mf][nf][1] + n0.y + bi0;
            float v2 = acc[mf][nf][2] + n1.x + bi8;
            float v3 = acc[mf][nf][3] + n1.y + bi8;
            float2 r0, r1;
            r0.x = (v0 >= 0.f) ? v0 : 0.2f * v0;
            r0.y = (v1 >= 0.f) ? v1 : 0.2f * v1;
            r1.x = (v2 >= 0.f) ? v2 : 0.2f * v2;
            r1.y = (v3 >= 0.f) ? v3 : 0.2f * v3;
            *(float2*)(out + o0) = r0;
            *(float2*)(out + o1) = r1;
        }
    }
}

// ---------------------------------------------------------------------------
extern "C" void kernel_launch(void* const* d_in, const int* in_sizes, int n_in,
                              void* d_out, int out_size) {
    const float* x      = (const float*)d_in[0];
    const float* w      = (const float*)d_in[1];
    const float* noise  = (const float*)d_in[2];
    const float* weight = (const float*)d_in[3];
    const float* aw     = (const float*)d_in[4];
    const float* ab     = (const float*)d_in[5];
    const float* bias   = (const float*)d_in[6];
    float* out = (float*)d_out;

    cudaFuncSetAttribute(conv_hmma, cudaFuncAttributeMaxDynamicSharedMemorySize,
                         SMEM_TOTAL);

    style_kernel<<<(B_ * CIN * 32 + 255) / 256, 256>>>(w, aw, ab);
    wsplit_kernel<<<dim3(COUT, B_), CIN>>>(weight);
    xsplitT_kernel<<<dim3(HW, B_), 512>>>(x);
    conv_hmma<<<dim3(16, 8, B_), 128, SMEM_TOTAL>>>(noise, bias, out);
}